// round 6
// baseline (speedup 1.0000x reference)
#include <cuda_runtime.h>
#include <cuda_fp16.h>
#include <math.h>
#include <stdint.h>

// out = LayerNorm(Re(FFT(x, axis=-1))), x: (4,4096,2048) fp32.
// Radix-2 split of the folded cosine transform:
//   s[c] = x[c]+x[2048-c] (c=1..1023), s[1024]=x[1024]; c=0 dropped (== mean)
//   E[k] = sum_{d=1..512} s[2d]   cos(pi k d   /512 )   (E[1024-k] =  E[k])
//   O[k] = sum_{d=0..511} s[2d+1] cos(pi k(2d+1)/1024)  (O[1024-k] = -O[k])
//   y-mu:  [k]=E+O, [1024-k]=E-O (k=0..511); [512] = sum s[2d](-1)^d (prep)
//   outer mirror y[2048-k]=y[k]; var = 0.5*(sum x^2 + sum x[c]x[-c]) - mu^2
// GEMM: M=16384, K=512 x2 phases, N=512, fp16/fp32 mma.sync, persistent CTAs
// with dynamic tile stealing (atomic counter) + cross-tile prologue overlap.

#define ROWS 16384
#define CDIM 2048
#define BM   128
#define BNK  64          // k-columns per CTA tile
#define BKC  64          // K chunk
#define NT   16          // chunks: 8 E + 8 O
#define STAGES 4
#define NTILES 1024      // 128 m-tiles x 8 k-tiles
#define NCTAS  296       // 2 per SM x 148
#define TBLOCKS 512      // table-init blocks (256 thr x 4 halfs)
#define EPS  1e-5f

__device__ __half g_S[(size_t)ROWS * 1024];  // [m][0..511]=s_even(d=1..512), [512..1023]=s_odd
__device__ __half g_T[(size_t)512 * 1024];   // [k][0..511]=Be, [512..1023]=Bo
__device__ float  g_rs[ROWS];
__device__ unsigned g_tile;

__device__ __forceinline__ uint32_t smem_u32(const void* p) {
    uint32_t a;
    asm("{ .reg .u64 t; cvta.to.shared.u64 t, %1; cvt.u32.u64 %0, t; }" : "=r"(a) : "l"(p));
    return a;
}
__device__ __forceinline__ void cp16(uint32_t s, const void* g) {
    asm volatile("cp.async.cg.shared.global [%0], [%1], 16;" :: "r"(s), "l"(g) : "memory");
}
#define CP_COMMIT() asm volatile("cp.async.commit_group;" ::: "memory")

__device__ __forceinline__ void ldm_x4(uint32_t* r, uint32_t a) {
    asm volatile("ldmatrix.sync.aligned.m8n8.x4.shared.b16 {%0,%1,%2,%3}, [%4];"
                 : "=r"(r[0]), "=r"(r[1]), "=r"(r[2]), "=r"(r[3]) : "r"(a));
}
__device__ __forceinline__ void mma16816(float* c, const uint32_t* a, const uint32_t* b) {
    asm volatile("mma.sync.aligned.m16n8k16.row.col.f32.f16.f16.f32 "
                 "{%0,%1,%2,%3}, {%4,%5,%6,%7}, {%8,%9}, {%0,%1,%2,%3};"
                 : "+f"(c[0]), "+f"(c[1]), "+f"(c[2]), "+f"(c[3])
                 : "r"(a[0]), "r"(a[1]), "r"(a[2]), "r"(a[3]), "r"(b[0]), "r"(b[1]));
}

// ---------------------------------------------------------------- prep + table
// blocks [0,ROWS): per-row fold/stats. blocks [ROWS, ROWS+TBLOCKS): cos tables
// (4 halfs per thread, uint2 stores). Block ROWS thread 0 resets the tile ctr.
__global__ __launch_bounds__(256) void prep_kernel(const float* __restrict__ x,
                                                   const float* __restrict__ gamma,
                                                   const float* __restrict__ beta,
                                                   float* __restrict__ out) {
    if (blockIdx.x >= ROWS) {
        int b = blockIdx.x - ROWS;
        if (b == 0 && threadIdx.x == 0) g_tile = 0u;
        int base = (b * 256 + threadIdx.x) * 4;     // half index, < 512*1024
        int k = base >> 10;
        int j0 = base & 1023;                       // j0..j0+3 share k (j0 % 4 == 0)
        __half h[4];
        #pragma unroll
        for (int q = 0; q < 4; q++) {
            int j = j0 + q;
            float v;
            if (j < 512) v = cospif((float)(k * (j + 1)) * (1.0f / 512.0f));
            else         v = cospif((float)(k * (2 * (j - 512) + 1)) * (1.0f / 1024.0f));
            h[q] = __float2half(v);
        }
        *(uint2*)(g_T + base) = *(const uint2*)h;
        return;
    }

    __shared__ float sx[CDIM];
    __shared__ float w1[8], w2[8], w3[8];
    int row = blockIdx.x;
    int tid = threadIdx.x;
    const float4* x4 = (const float4*)(x + (size_t)row * CDIM);

    float4 va = x4[tid];
    float4 vb = x4[tid + 256];
    ((float4*)sx)[tid] = va;
    ((float4*)sx)[tid + 256] = vb;
    float sumsq = va.x * va.x + va.y * va.y + va.z * va.z + va.w * va.w
                + vb.x * vb.x + vb.y * vb.y + vb.z * vb.z + vb.w * vb.w;
    __syncthreads();

    float sumrev = 0.0f;
    #pragma unroll
    for (int i = tid; i < CDIM; i += 256) {
        sumrev += sx[i] * sx[(CDIM - i) & (CDIM - 1)];
    }

    // E[512] = sum_{d=1..512} s[2d]*(-1)^d
    float e512 = 0.0f;
    #pragma unroll
    for (int d = tid + 1; d <= 512; d += 256) {
        float s2d = (d == 512) ? sx[1024] : (sx[2 * d] + sx[CDIM - 2 * d]);
        e512 += (d & 1) ? -s2d : s2d;
    }

    // fold + split: thread t writes S[4t..4t+3] as one uint2
    {
        __half h[4];
        #pragma unroll
        for (int q = 0; q < 4; q++) {
            int j = 4 * tid + q;
            int c = (j < 512) ? (2 * j + 2) : (2 * (j - 512) + 1);
            float v = (c == 1024) ? sx[1024] : (sx[c] + sx[CDIM - c]);
            h[q] = __float2half(v);
        }
        *(uint2*)(g_S + (size_t)row * 1024 + 4 * tid) = *(const uint2*)h;
    }

    #pragma unroll
    for (int o = 16; o > 0; o >>= 1) {
        sumsq  += __shfl_xor_sync(0xffffffffu, sumsq, o);
        sumrev += __shfl_xor_sync(0xffffffffu, sumrev, o);
        e512   += __shfl_xor_sync(0xffffffffu, e512, o);
    }
    if ((tid & 31) == 0) { w1[tid >> 5] = sumsq; w2[tid >> 5] = sumrev; w3[tid >> 5] = e512; }
    __syncthreads();
    if (tid == 0) {
        float a = 0.0f, b = 0.0f, e5 = 0.0f;
        #pragma unroll
        for (int i = 0; i < 8; i++) { a += w1[i]; b += w2[i]; e5 += w3[i]; }
        float mu = sx[0];
        float var = 0.5f * (a + b) - mu * mu;
        float rs = rsqrtf(var + EPS);
        g_rs[row] = rs;
        float z = e5 * rs;                      // y[512]-mu = E[512]
        float* orow = out + (size_t)row * CDIM;
        orow[512]  = z * gamma[512]  + beta[512];
        orow[1536] = z * gamma[1536] + beta[1536];
    }
}

// ---------------------------------------------------------------- GEMM + LN
// stage: A 128x64 fp16 (16KB) + B 64x64 fp16 (8KB) = 24KB; rows 128B, xor swizzle
#define STAGE_BYTES 24576
#define SMEM_SZ (STAGES * STAGE_BYTES)

__global__ __launch_bounds__(256, 2) void gemm_ln_kernel(const float* __restrict__ gamma,
                                                         const float* __restrict__ beta,
                                                         float* __restrict__ out) {
    extern __shared__ __align__(1024) uint8_t smem[];
    __shared__ unsigned s_tile;
    const uint32_t sbase = smem_u32(smem);
    const int tid = threadIdx.x;
    const int wid = tid >> 5;
    const int lane = tid & 31;

    // ---- producer mapping
    const int arow = tid >> 1;
    const int ac0 = (tid & 1) * 4;
    const uint32_t aso = (uint32_t)arow * 128u;
    const int arx = arow & 7;
    const int brow = tid >> 2;
    const int bc0 = (tid & 3) * 2;
    const uint32_t bso = (uint32_t)brow * 128u;
    const int brx = brow & 7;

    // ---- consumer mapping: 8 warps = 4m x 2n, warp tile 32m x 32n
    const int wm = wid & 3;
    const int wn = wid >> 2;
    uint32_t rowa_off[2];
    {
        int rbase = wm * 32 + (lane & 15);
        rowa_off[0] = (uint32_t)rbase * 128u;
        rowa_off[1] = (uint32_t)(rbase + 16) * 128u;
    }
    const int rxa = lane & 7;
    const int csel_a = lane >> 4;
    uint32_t rowb_off[2];
    {
        int nb = wn * 32 + ((lane >> 4) << 3) + (lane & 7);
        rowb_off[0] = (uint32_t)nb * 128u;
        rowb_off[1] = (uint32_t)(nb + 16) * 128u;
    }
    const int rxb = lane & 7;
    const int csel_b = (lane >> 3) & 1;

    auto load_stage = [&](int stage, int t, int m0, int k0) {
        uint32_t sA = sbase + (uint32_t)stage * STAGE_BYTES;
        uint32_t sB = sA + 16384u;
        int koff = (t >> 3) * 512 + (t & 7) * BKC;
        const __half* pa = g_S + (size_t)(m0 + arow) * 1024 + ac0 * 8 + koff;
        const __half* pb = g_T + (size_t)(k0 + brow) * 1024 + bc0 * 8 + koff;
        #pragma unroll
        for (int i = 0; i < 4; i++)
            cp16(sA + aso + (uint32_t)(((ac0 + i) ^ arx) << 4), pa + i * 8);
        #pragma unroll
        for (int i = 0; i < 2; i++)
            cp16(sB + bso + (uint32_t)(((bc0 + i) ^ brx) << 4), pb + i * 8);
        CP_COMMIT();
    };

    float accE[2][4][4], accO[2][4][4];

    // chunk step: wait -> barrier -> prefetch t+3 -> compute into acc
    auto step = [&](float (&acc)[2][4][4], int t, int m0, int k0) {
        if (t < NT - 2)       asm volatile("cp.async.wait_group 2;" ::: "memory");
        else if (t == NT - 2) asm volatile("cp.async.wait_group 1;" ::: "memory");
        else                  asm volatile("cp.async.wait_group 0;" ::: "memory");
        __syncthreads();
        if (t + 3 < NT) load_stage((t + 3) & (STAGES - 1), t + 3, m0, k0);

        uint32_t stA = sbase + (uint32_t)(t & (STAGES - 1)) * STAGE_BYTES;
        uint32_t stB = stA + 16384u;
        #pragma unroll
        for (int ks = 0; ks < 4; ks++) {
            uint32_t a[2][4], b[2][4];
            int cha = (2 * ks + csel_a) ^ rxa;
            ldm_x4(a[0], stA + rowa_off[0] + (uint32_t)(cha << 4));
            ldm_x4(a[1], stA + rowa_off[1] + (uint32_t)(cha << 4));
            int chb = (2 * ks + csel_b) ^ rxb;
            ldm_x4(b[0], stB + rowb_off[0] + (uint32_t)(chb << 4));
            ldm_x4(b[1], stB + rowb_off[1] + (uint32_t)(chb << 4));
            #pragma unroll
            for (int mf = 0; mf < 2; mf++) {
                mma16816(acc[mf][0], a[mf], &b[0][0]);
                mma16816(acc[mf][1], a[mf], &b[0][2]);
                mma16816(acc[mf][2], a[mf], &b[1][0]);
                mma16816(acc[mf][3], a[mf], &b[1][2]);
            }
        }
    };

    // ---- first tile
    if (tid == 0) s_tile = atomicAdd(&g_tile, 1u);
    __syncthreads();
    unsigned tile = s_tile;
    if (tile >= NTILES) return;
    int m0 = (int)(tile >> 3) * BM;
    int k0 = (int)(tile & 7) * BNK;

    load_stage(0, 0, m0, k0);
    load_stage(1, 1, m0, k0);
    load_stage(2, 2, m0, k0);

    while (true) {
        #pragma unroll
        for (int i = 0; i < 2; i++)
            #pragma unroll
            for (int j = 0; j < 4; j++)
                #pragma unroll
                for (int r = 0; r < 4; r++) { accE[i][j][r] = 0.0f; accO[i][j][r] = 0.0f; }

        #pragma unroll 2
        for (int t = 0; t < 8; t++)  step(accE, t, m0, k0);
        #pragma unroll 2
        for (int t = 8; t < 16; t++) step(accO, t, m0, k0);

        // grab next tile; start its prologue loads before the epilogue
        __syncthreads();
        if (tid == 0) s_tile = atomicAdd(&g_tile, 1u);
        __syncthreads();
        unsigned nxt = s_tile;
        int nm0 = 0, nk0 = 0;
        if (nxt < NTILES) {
            nm0 = (int)(nxt >> 3) * BM;
            nk0 = (int)(nxt & 7) * BNK;
            load_stage(0, 0, nm0, nk0);
            load_stage(1, 1, nm0, nk0);
            load_stage(2, 2, nm0, nk0);
        }

        // ---- epilogue: butterfly + LN + 4-region store
        float rsv[2][2];
        #pragma unroll
        for (int mf = 0; mf < 2; mf++) {
            int r0 = m0 + wm * 32 + mf * 16 + (lane >> 2);
            rsv[mf][0] = g_rs[r0];
            rsv[mf][1] = g_rs[r0 + 8];
        }
        const int kw = k0 + wn * 32 + 2 * (lane & 3);
        #pragma unroll
        for (int nf = 0; nf < 4; nf++) {
            int k = kw + nf * 8;                       // even, 0..510
            float g0 = __ldg(gamma + k),     be0 = __ldg(beta + k);
            float g1 = __ldg(gamma + k + 1), be1 = __ldg(beta + k + 1);
            float gm1 = __ldg(gamma + 2047 - k), bm1 = __ldg(beta + 2047 - k);
            float gm0 = 0.0f, bm0 = 0.0f;
            if (k > 0) { gm0 = __ldg(gamma + 2048 - k); bm0 = __ldg(beta + 2048 - k); }
            float gb0 = __ldg(gamma + 1024 - k), bb0 = __ldg(beta + 1024 - k);
            float gb1 = __ldg(gamma + 1023 - k), bb1 = __ldg(beta + 1023 - k);
            float gf0 = __ldg(gamma + 1024 + k), bf0 = __ldg(beta + 1024 + k);
            float gf1 = __ldg(gamma + 1025 + k), bf1 = __ldg(beta + 1025 + k);
            #pragma unroll
            for (int mf = 0; mf < 2; mf++) {
                int rbase = m0 + wm * 32 + mf * 16 + (lane >> 2);
                #pragma unroll
                for (int rp = 0; rp < 2; rp++) {
                    float* o = out + (size_t)(rbase + rp * 8) * CDIM;
                    float E0 = accE[mf][nf][rp * 2],     O0 = accO[mf][nf][rp * 2];
                    float E1 = accE[mf][nf][rp * 2 + 1], O1 = accO[mf][nf][rp * 2 + 1];
                    float r = rsv[mf][rp];
                    float z0 = (E0 + O0) * r, z1 = (E1 + O1) * r;
                    float w0 = (E0 - O0) * r, w1 = (E1 - O1) * r;
                    *(float2*)(o + k) = make_float2(z0 * g0 + be0, z1 * g1 + be1);
                    o[2047 - k] = z1 * gm1 + bm1;
                    if (k > 0) o[2048 - k] = z0 * gm0 + bm0;
                    o[1024 - k] = w0 * gb0 + bb0;
                    o[1023 - k] = w1 * gb1 + bb1;
                    if (k > 0) *(float2*)(o + 1024 + k) = make_float2(w0 * gf0 + bf0, w1 * gf1 + bf1);
                    else       o[1025] = w1 * gf1 + bf1;
                }
            }
        }

        if (nxt >= NTILES) return;
        m0 = nm0; k0 = nk0;
    }
}

// ---------------------------------------------------------------- launch
extern "C" void kernel_launch(void* const* d_in, const int* in_sizes, int n_in,
                              void* d_out, int out_size) {
    const float* x     = (const float*)d_in[0];
    const float* gamma = (const float*)d_in[1];
    const float* beta  = (const float*)d_in[2];
    float* out = (float*)d_out;

    prep_kernel<<<ROWS + TBLOCKS, 256>>>(x, gamma, beta, out);

    cudaFuncSetAttribute(gemm_ln_kernel, cudaFuncAttributeMaxDynamicSharedMemorySize, SMEM_SZ);
    gemm_ln_kernel<<<NCTAS, 256, SMEM_SZ>>>(gamma, beta, out);
}

// round 7
// speedup vs baseline: 1.0431x; 1.0431x over previous
#include <cuda_runtime.h>
#include <cuda_fp16.h>
#include <math.h>
#include <stdint.h>

// out = LayerNorm(Re(FFT(x, axis=-1))), x: (4,4096,2048) fp32.
// Radix-2 split of the folded cosine transform:
//   s[c] = x[c]+x[2048-c] (c=1..1023), s[1024]=x[1024]; c=0 dropped (== mean)
//   E[k] = sum_{d=1..512} s[2d]   cos(pi k d   /512 )   (E[1024-k] =  E[k])
//   O[k] = sum_{d=0..511} s[2d+1] cos(pi k(2d+1)/1024)  (O[1024-k] = -O[k])
//   y-mu:  [k]=E+O, [1024-k]=E-O (k=0..511); [512] = sum s[2d](-1)^d (prep)
//   outer mirror y[2048-k]=y[k]; var = 0.5*(sum x^2 + sum x[c]x[-c]) - mu^2
// GEMM: M=16384, K=512 x2 phases, N=512, fp16/fp32 mma.sync.
// CTA tile 64m x 64n (2048 CTAs -> ~1% wave tail), 8 warps (warp 16m x 32n),
// dual-phase accumulators, 4-stage cp.async pipeline, 3 CTAs/SM target.

#define ROWS 16384
#define CDIM 2048
#define BM   64
#define BNK  64          // k-columns per CTA tile
#define BKC  64          // K chunk
#define NT   16          // chunks: 8 E + 8 O
#define STAGES 4
#define TBLOCKS 512      // table-init blocks (256 thr x 4 halfs)
#define EPS  1e-5f

__device__ __half g_S[(size_t)ROWS * 1024];  // [m][0..511]=s_even(d=1..512), [512..1023]=s_odd
__device__ __half g_T[(size_t)512 * 1024];   // [k][0..511]=Be, [512..1023]=Bo
__device__ float  g_rs[ROWS];

__device__ __forceinline__ uint32_t smem_u32(const void* p) {
    uint32_t a;
    asm("{ .reg .u64 t; cvta.to.shared.u64 t, %1; cvt.u32.u64 %0, t; }" : "=r"(a) : "l"(p));
    return a;
}
__device__ __forceinline__ void cp16(uint32_t s, const void* g) {
    asm volatile("cp.async.cg.shared.global [%0], [%1], 16;" :: "r"(s), "l"(g) : "memory");
}
#define CP_COMMIT() asm volatile("cp.async.commit_group;" ::: "memory")

__device__ __forceinline__ void ldm_x4(uint32_t* r, uint32_t a) {
    asm volatile("ldmatrix.sync.aligned.m8n8.x4.shared.b16 {%0,%1,%2,%3}, [%4];"
                 : "=r"(r[0]), "=r"(r[1]), "=r"(r[2]), "=r"(r[3]) : "r"(a));
}
__device__ __forceinline__ void mma16816(float* c, const uint32_t* a, const uint32_t* b) {
    asm volatile("mma.sync.aligned.m16n8k16.row.col.f32.f16.f16.f32 "
                 "{%0,%1,%2,%3}, {%4,%5,%6,%7}, {%8,%9}, {%0,%1,%2,%3};"
                 : "+f"(c[0]), "+f"(c[1]), "+f"(c[2]), "+f"(c[3])
                 : "r"(a[0]), "r"(a[1]), "r"(a[2]), "r"(a[3]), "r"(b[0]), "r"(b[1]));
}

// ---------------------------------------------------------------- prep + table
// blocks [0,ROWS): per-row fold/stats. blocks [ROWS, ROWS+TBLOCKS): cos tables
// (4 halfs per thread, uint2 stores).
// Be[k][j]=cospi(k*(j+1)/512); Bo[k][d]=cospi(k*(2d+1)/1024); args exact fp32.
__global__ __launch_bounds__(256) void prep_kernel(const float* __restrict__ x,
                                                   const float* __restrict__ gamma,
                                                   const float* __restrict__ beta,
                                                   float* __restrict__ out) {
    if (blockIdx.x >= ROWS) {
        int b = blockIdx.x - ROWS;
        int base = (b * 256 + threadIdx.x) * 4;     // half index, < 512*1024
        int k = base >> 10;
        int j0 = base & 1023;                       // j0..j0+3 share k
        __half h[4];
        #pragma unroll
        for (int q = 0; q < 4; q++) {
            int j = j0 + q;
            float v;
            if (j < 512) v = cospif((float)(k * (j + 1)) * (1.0f / 512.0f));
            else         v = cospif((float)(k * (2 * (j - 512) + 1)) * (1.0f / 1024.0f));
            h[q] = __float2half(v);
        }
        *(uint2*)(g_T + base) = *(const uint2*)h;
        return;
    }

    __shared__ float sx[CDIM];
    __shared__ float w1[8], w2[8], w3[8];
    int row = blockIdx.x;
    int tid = threadIdx.x;
    const float4* x4 = (const float4*)(x + (size_t)row * CDIM);

    float4 va = x4[tid];
    float4 vb = x4[tid + 256];
    ((float4*)sx)[tid] = va;
    ((float4*)sx)[tid + 256] = vb;
    float sumsq = va.x * va.x + va.y * va.y + va.z * va.z + va.w * va.w
                + vb.x * vb.x + vb.y * vb.y + vb.z * vb.z + vb.w * vb.w;
    __syncthreads();

    float sumrev = 0.0f;
    #pragma unroll
    for (int i = tid; i < CDIM; i += 256) {
        sumrev += sx[i] * sx[(CDIM - i) & (CDIM - 1)];
    }

    // E[512] = sum_{d=1..512} s[2d]*(-1)^d
    float e512 = 0.0f;
    #pragma unroll
    for (int d = tid + 1; d <= 512; d += 256) {
        float s2d = (d == 512) ? sx[1024] : (sx[2 * d] + sx[CDIM - 2 * d]);
        e512 += (d & 1) ? -s2d : s2d;
    }

    // fold + split: thread t writes S[4t..4t+3] as one uint2
    {
        __half h[4];
        #pragma unroll
        for (int q = 0; q < 4; q++) {
            int j = 4 * tid + q;
            int c = (j < 512) ? (2 * j + 2) : (2 * (j - 512) + 1);
            float v = (c == 1024) ? sx[1024] : (sx[c] + sx[CDIM - c]);
            h[q] = __float2half(v);
        }
        *(uint2*)(g_S + (size_t)row * 1024 + 4 * tid) = *(const uint2*)h;
    }

    #pragma unroll
    for (int o = 16; o > 0; o >>= 1) {
        sumsq  += __shfl_xor_sync(0xffffffffu, sumsq, o);
        sumrev += __shfl_xor_sync(0xffffffffu, sumrev, o);
        e512   += __shfl_xor_sync(0xffffffffu, e512, o);
    }
    if ((tid & 31) == 0) { w1[tid >> 5] = sumsq; w2[tid >> 5] = sumrev; w3[tid >> 5] = e512; }
    __syncthreads();
    if (tid == 0) {
        float a = 0.0f, b = 0.0f, e5 = 0.0f;
        #pragma unroll
        for (int i = 0; i < 8; i++) { a += w1[i]; b += w2[i]; e5 += w3[i]; }
        float mu = sx[0];
        float var = 0.5f * (a + b) - mu * mu;
        float rs = rsqrtf(var + EPS);
        g_rs[row] = rs;
        float z = e5 * rs;                      // y[512]-mu = E[512]
        float* orow = out + (size_t)row * CDIM;
        orow[512]  = z * gamma[512]  + beta[512];
        orow[1536] = z * gamma[1536] + beta[1536];
    }
}

// ---------------------------------------------------------------- GEMM + LN
// stage: A 64x64 fp16 (8KB) + B 64x64 fp16 (8KB) = 16KB; rows 128B, xor swizzle
#define STAGE_BYTES 16384
#define SMEM_SZ (STAGES * STAGE_BYTES)

__global__ __launch_bounds__(256, 3) void gemm_ln_kernel(const float* __restrict__ gamma,
                                                         const float* __restrict__ beta,
                                                         float* __restrict__ out) {
    extern __shared__ __align__(1024) uint8_t smem[];
    const uint32_t sbase = smem_u32(smem);
    const int tid = threadIdx.x;
    const int wid = tid >> 5;
    const int lane = tid & 31;
    const int m0 = blockIdx.y * BM;
    const int k0 = blockIdx.x * BNK;     // k-column tile base (0..511)

    // ---- producers: 64 rows x 8 chunks(16B) each for A and B; 2 chunks/thread
    const int prow = tid >> 2;                 // 0..63
    const int pc0 = (tid & 3) * 2;             // chunk pair
    const __half* gA = g_S + (size_t)(m0 + prow) * 1024 + pc0 * 8;
    const __half* gB = g_T + (size_t)(k0 + prow) * 1024 + pc0 * 8;
    const uint32_t pso = (uint32_t)prow * 128u;
    const int prx = prow & 7;

    // ---- consumers: 8 warps = 4 (m) x 2 (n); warp tile 16m x 32n
    const int wm = wid & 3;
    const int wn = wid >> 2;
    const uint32_t rowa_off = (uint32_t)(wm * 16 + (lane & 15)) * 128u;
    const int rxa = lane & 7;
    const int csel_a = lane >> 4;
    uint32_t rowb_off[2];
    {
        int nb = wn * 32 + ((lane >> 4) << 3) + (lane & 7);
        rowb_off[0] = (uint32_t)nb * 128u;
        rowb_off[1] = (uint32_t)(nb + 16) * 128u;
    }
    const int rxb = lane & 7;
    const int csel_b = (lane >> 3) & 1;

    float accE[4][4], accO[4][4];
    #pragma unroll
    for (int j = 0; j < 4; j++)
        #pragma unroll
        for (int r = 0; r < 4; r++) { accE[j][r] = 0.0f; accO[j][r] = 0.0f; }

    auto load_stage = [&](int stage, int t) {
        uint32_t sA = sbase + (uint32_t)stage * STAGE_BYTES;
        uint32_t sB = sA + 8192u;
        int koff = (t >> 3) * 512 + (t & 7) * BKC;    // phase*512 + kc*64
        const __half* pa = gA + koff;
        const __half* pb = gB + koff;
        #pragma unroll
        for (int i = 0; i < 2; i++) {
            uint32_t so = pso + (uint32_t)(((pc0 + i) ^ prx) << 4);
            cp16(sA + so, pa + i * 8);
            cp16(sB + so, pb + i * 8);
        }
        CP_COMMIT();
    };

    load_stage(0, 0);
    load_stage(1, 1);
    load_stage(2, 2);

    for (int t = 0; t < NT; t++) {
        if (t < NT - 2)       asm volatile("cp.async.wait_group 2;" ::: "memory");
        else if (t == NT - 2) asm volatile("cp.async.wait_group 1;" ::: "memory");
        else                  asm volatile("cp.async.wait_group 0;" ::: "memory");
        __syncthreads();
        if (t + 3 < NT) load_stage((t + 3) & (STAGES - 1), t + 3);

        uint32_t stA = sbase + (uint32_t)(t & (STAGES - 1)) * STAGE_BYTES;
        uint32_t stB = stA + 8192u;

        #pragma unroll
        for (int ks = 0; ks < 4; ks++) {
            uint32_t a[4], b[2][4];
            int cha = (2 * ks + csel_a) ^ rxa;
            ldm_x4(a, stA + rowa_off + (uint32_t)(cha << 4));
            int chb = (2 * ks + csel_b) ^ rxb;
            ldm_x4(b[0], stB + rowb_off[0] + (uint32_t)(chb << 4));
            ldm_x4(b[1], stB + rowb_off[1] + (uint32_t)(chb << 4));
            if (t < 8) {
                mma16816(accE[0], a, &b[0][0]);
                mma16816(accE[1], a, &b[0][2]);
                mma16816(accE[2], a, &b[1][0]);
                mma16816(accE[3], a, &b[1][2]);
            } else {
                mma16816(accO[0], a, &b[0][0]);
                mma16816(accO[1], a, &b[0][2]);
                mma16816(accO[2], a, &b[1][0]);
                mma16816(accO[3], a, &b[1][2]);
            }
        }
    }

    // ---- epilogue: butterfly + LN + 4-region store
    const int r0 = m0 + wm * 16 + (lane >> 2);
    const float rs0 = g_rs[r0];
    const float rs1 = g_rs[r0 + 8];
    const int kw = k0 + wn * 32 + 2 * (lane & 3);
    #pragma unroll
    for (int nf = 0; nf < 4; nf++) {
        int k = kw + nf * 8;                       // even, 0..510
        float g0 = __ldg(gamma + k),     be0 = __ldg(beta + k);
        float g1 = __ldg(gamma + k + 1), be1 = __ldg(beta + k + 1);
        float gm1 = __ldg(gamma + 2047 - k), bm1 = __ldg(beta + 2047 - k);
        float gm0 = 0.0f, bm0 = 0.0f;
        if (k > 0) { gm0 = __ldg(gamma + 2048 - k); bm0 = __ldg(beta + 2048 - k); }
        float gb0 = __ldg(gamma + 1024 - k), bb0 = __ldg(beta + 1024 - k);
        float gb1 = __ldg(gamma + 1023 - k), bb1 = __ldg(beta + 1023 - k);
        float gf0 = __ldg(gamma + 1024 + k), bf0 = __ldg(beta + 1024 + k);
        float gf1 = __ldg(gamma + 1025 + k), bf1 = __ldg(beta + 1025 + k);
        #pragma unroll
        for (int rp = 0; rp < 2; rp++) {
            float* o = out + (size_t)(r0 + rp * 8) * CDIM;
            float E0 = accE[nf][rp * 2],     O0 = accO[nf][rp * 2];
            float E1 = accE[nf][rp * 2 + 1], O1 = accO[nf][rp * 2 + 1];
            float r = rp ? rs1 : rs0;
            float z0 = (E0 + O0) * r, z1 = (E1 + O1) * r;
            float w0 = (E0 - O0) * r, w1 = (E1 - O1) * r;
            *(float2*)(o + k) = make_float2(z0 * g0 + be0, z1 * g1 + be1);
            o[2047 - k] = z1 * gm1 + bm1;
            if (k > 0) o[2048 - k] = z0 * gm0 + bm0;
            o[1024 - k] = w0 * gb0 + bb0;
            o[1023 - k] = w1 * gb1 + bb1;
            if (k > 0) *(float2*)(o + 1024 + k) = make_float2(w0 * gf0 + bf0, w1 * gf1 + bf1);
            else       o[1025] = w1 * gf1 + bf1;
        }
    }
}

// ---------------------------------------------------------------- launch
extern "C" void kernel_launch(void* const* d_in, const int* in_sizes, int n_in,
                              void* d_out, int out_size) {
    const float* x     = (const float*)d_in[0];
    const float* gamma = (const float*)d_in[1];
    const float* beta  = (const float*)d_in[2];
    float* out = (float*)d_out;

    prep_kernel<<<ROWS + TBLOCKS, 256>>>(x, gamma, beta, out);

    cudaFuncSetAttribute(gemm_ln_kernel, cudaFuncAttributeMaxDynamicSharedMemorySize, SMEM_SZ);
    dim3 grid(512 / BNK, ROWS / BM);   // (8, 256): k fastest -> A rows shared in L2
    gemm_ln_kernel<<<grid, 256, SMEM_SZ>>>(gamma, beta, out);
}

// round 8
// speedup vs baseline: 1.1776x; 1.1289x over previous
#include <cuda_runtime.h>
#include <cuda_fp16.h>
#include <math.h>
#include <stdint.h>

// out = LayerNorm(Re(FFT(x, axis=-1))), x: (4,4096,2048) fp32.
// Radix-2 split of the folded cosine transform:
//   s[c] = x[c]+x[2048-c] (c=1..1023), s[1024]=x[1024]; c=0 dropped (== mean)
//   E[k] = sum_{d=1..512} s[2d]   cos(pi k d   /512 )   (E[1024-k] =  E[k])
//   O[k] = sum_{d=0..511} s[2d+1] cos(pi k(2d+1)/1024)  (O[1024-k] = -O[k])
//   y-mu:  [k]=E+O, [1024-k]=E-O (k=0..511); [512] = sum s[2d](-1)^d (prep)
//   outer mirror y[2048-k]=y[k]; var = 0.5*(sum x^2 + sum x[c]x[-c]) - mu^2
// GEMM: M=16384, K=512 x2 phases, N=512, fp16/fp32 mma.sync.
// CTA tile 64m x 64n (2048 CTAs -> ~1% wave tail), 8 warps (warp 16m x 32n),
// dual-phase accumulators, 4-stage cp.async pipeline, 3 CTAs/SM.

#define ROWS 16384
#define CDIM 2048
#define BM   64
#define BNK  64          // k-columns per CTA tile
#define BKC  64          // K chunk
#define NT   16          // chunks: 8 E + 8 O
#define STAGES 4
#define TBLOCKS 2048     // table-init blocks (1 half per thread, R5-style)
#define EPS  1e-5f

__device__ __half g_S[(size_t)ROWS * 1024];  // [m][0..511]=s_even(d=1..512), [512..1023]=s_odd
__device__ __half g_T[(size_t)512 * 1024];   // [k][0..511]=Be, [512..1023]=Bo
__device__ float  g_rs[ROWS];

__device__ __forceinline__ uint32_t smem_u32(const void* p) {
    uint32_t a;
    asm("{ .reg .u64 t; cvta.to.shared.u64 t, %1; cvt.u32.u64 %0, t; }" : "=r"(a) : "l"(p));
    return a;
}
__device__ __forceinline__ void cp16(uint32_t s, const void* g) {
    asm volatile("cp.async.cg.shared.global [%0], [%1], 16;" :: "r"(s), "l"(g) : "memory");
}
#define CP_COMMIT() asm volatile("cp.async.commit_group;" ::: "memory")

__device__ __forceinline__ void ldm_x4(uint32_t* r, uint32_t a) {
    asm volatile("ldmatrix.sync.aligned.m8n8.x4.shared.b16 {%0,%1,%2,%3}, [%4];"
                 : "=r"(r[0]), "=r"(r[1]), "=r"(r[2]), "=r"(r[3]) : "r"(a));
}
__device__ __forceinline__ void mma16816(float* c, const uint32_t* a, const uint32_t* b) {
    asm volatile("mma.sync.aligned.m16n8k16.row.col.f32.f16.f16.f32 "
                 "{%0,%1,%2,%3}, {%4,%5,%6,%7}, {%8,%9}, {%0,%1,%2,%3};"
                 : "+f"(c[0]), "+f"(c[1]), "+f"(c[2]), "+f"(c[3])
                 : "r"(a[0]), "r"(a[1]), "r"(a[2]), "r"(a[3]), "r"(b[0]), "r"(b[1]));
}

// ---------------------------------------------------------------- prep + table
// blocks [0,ROWS): per-row fold/stats (R5-proven access pattern).
// blocks [ROWS, ROWS+TBLOCKS): cos tables, 1 half per thread.
// Be[k][j]=cospi(k*(j+1)/512); Bo[k][d]=cospi(k*(2d+1)/1024); args exact fp32.
__global__ __launch_bounds__(256) void prep_kernel(const float* __restrict__ x,
                                                   const float* __restrict__ gamma,
                                                   const float* __restrict__ beta,
                                                   float* __restrict__ out) {
    if (blockIdx.x >= ROWS) {
        int idx = (blockIdx.x - ROWS) * 256 + threadIdx.x;   // < 512*1024
        int k = idx >> 10;
        int j = idx & 1023;
        float v;
        if (j < 512) v = cospif((float)(k * (j + 1)) * (1.0f / 512.0f));
        else         v = cospif((float)(k * (2 * (j - 512) + 1)) * (1.0f / 1024.0f));
        g_T[idx] = __float2half(v);
        return;
    }

    __shared__ float sx[CDIM];
    __shared__ float w1[8], w2[8], w3[8];
    int row = blockIdx.x;
    int tid = threadIdx.x;
    const float4* x4 = (const float4*)(x + (size_t)row * CDIM);

    float4 va = x4[tid];
    float4 vb = x4[tid + 256];
    ((float4*)sx)[tid] = va;
    ((float4*)sx)[tid + 256] = vb;
    float sumsq = va.x * va.x + va.y * va.y + va.z * va.z + va.w * va.w
                + vb.x * vb.x + vb.y * vb.y + vb.z * vb.z + vb.w * vb.w;
    __syncthreads();

    float sumrev = 0.0f;
    #pragma unroll
    for (int i = tid; i < CDIM; i += 256) {
        sumrev += sx[i] * sx[(CDIM - i) & (CDIM - 1)];
    }

    // E[512] = sum_{d=1..512} s[2d]*(-1)^d
    float e512 = 0.0f;
    for (int d = tid + 1; d <= 512; d += 256) {
        float s2d = (d == 512) ? sx[1024] : (sx[2 * d] + sx[CDIM - 2 * d]);
        e512 += (d & 1) ? -s2d : s2d;
    }

    // fold + split (R5 pattern: stride-256 thread mapping, 2-way conflicts max)
    __half* Sr = g_S + (size_t)row * 1024;
    #pragma unroll
    for (int j = tid; j < 1024; j += 256) {
        int c = (j < 512) ? (2 * j + 2) : (2 * (j - 512) + 1);
        float v = (c == 1024) ? sx[1024] : (sx[c] + sx[CDIM - c]);
        Sr[j] = __float2half(v);
    }

    #pragma unroll
    for (int o = 16; o > 0; o >>= 1) {
        sumsq  += __shfl_xor_sync(0xffffffffu, sumsq, o);
        sumrev += __shfl_xor_sync(0xffffffffu, sumrev, o);
        e512   += __shfl_xor_sync(0xffffffffu, e512, o);
    }
    if ((tid & 31) == 0) { w1[tid >> 5] = sumsq; w2[tid >> 5] = sumrev; w3[tid >> 5] = e512; }
    __syncthreads();
    if (tid == 0) {
        float a = 0.0f, b = 0.0f, e5 = 0.0f;
        #pragma unroll
        for (int i = 0; i < 8; i++) { a += w1[i]; b += w2[i]; e5 += w3[i]; }
        float mu = sx[0];
        float var = 0.5f * (a + b) - mu * mu;
        float rs = rsqrtf(var + EPS);
        g_rs[row] = rs;
        float z = e5 * rs;                      // y[512]-mu = E[512]
        float* orow = out + (size_t)row * CDIM;
        orow[512]  = z * gamma[512]  + beta[512];
        orow[1536] = z * gamma[1536] + beta[1536];
    }
}

// ---------------------------------------------------------------- GEMM + LN
// stage: A 64x64 fp16 (8KB) + B 64x64 fp16 (8KB) = 16KB; rows 128B, xor swizzle
#define STAGE_BYTES 16384
#define SMEM_SZ (STAGES * STAGE_BYTES)

__global__ __launch_bounds__(256, 3) void gemm_ln_kernel(const float* __restrict__ gamma,
                                                         const float* __restrict__ beta,
                                                         float* __restrict__ out) {
    extern __shared__ __align__(1024) uint8_t smem[];
    const uint32_t sbase = smem_u32(smem);
    const int tid = threadIdx.x;
    const int wid = tid >> 5;
    const int lane = tid & 31;
    const int m0 = blockIdx.y * BM;
    const int k0 = blockIdx.x * BNK;     // k-column tile base (0..511)

    // ---- producers: 64 rows x 8 chunks(16B) each for A and B; 2 chunks/thread
    const int prow = tid >> 2;                 // 0..63
    const int pc0 = (tid & 3) * 2;             // chunk pair
    const __half* gA = g_S + (size_t)(m0 + prow) * 1024 + pc0 * 8;
    const __half* gB = g_T + (size_t)(k0 + prow) * 1024 + pc0 * 8;
    const uint32_t pso = (uint32_t)prow * 128u;
    const int prx = prow & 7;

    // ---- consumers: 8 warps = 4 (m) x 2 (n); warp tile 16m x 32n
    const int wm = wid & 3;
    const int wn = wid >> 2;
    const uint32_t rowa_off = (uint32_t)(wm * 16 + (lane & 15)) * 128u;
    const int rxa = lane & 7;
    const int csel_a = lane >> 4;
    uint32_t rowb_off[2];
    {
        int nb = wn * 32 + ((lane >> 4) << 3) + (lane & 7);
        rowb_off[0] = (uint32_t)nb * 128u;
        rowb_off[1] = (uint32_t)(nb + 16) * 128u;
    }
    const int rxb = lane & 7;
    const int csel_b = (lane >> 3) & 1;

    float accE[4][4], accO[4][4];
    #pragma unroll
    for (int j = 0; j < 4; j++)
        #pragma unroll
        for (int r = 0; r < 4; r++) { accE[j][r] = 0.0f; accO[j][r] = 0.0f; }

    auto load_stage = [&](int stage, int t) {
        uint32_t sA = sbase + (uint32_t)stage * STAGE_BYTES;
        uint32_t sB = sA + 8192u;
        int koff = (t >> 3) * 512 + (t & 7) * BKC;    // phase*512 + kc*64
        const __half* pa = gA + koff;
        const __half* pb = gB + koff;
        #pragma unroll
        for (int i = 0; i < 2; i++) {
            uint32_t so = pso + (uint32_t)(((pc0 + i) ^ prx) << 4);
            cp16(sA + so, pa + i * 8);
            cp16(sB + so, pb + i * 8);
        }
        CP_COMMIT();
    };

    load_stage(0, 0);
    load_stage(1, 1);
    load_stage(2, 2);

    for (int t = 0; t < NT; t++) {
        if (t < NT - 2)       asm volatile("cp.async.wait_group 2;" ::: "memory");
        else if (t == NT - 2) asm volatile("cp.async.wait_group 1;" ::: "memory");
        else                  asm volatile("cp.async.wait_group 0;" ::: "memory");
        __syncthreads();
        if (t + 3 < NT) load_stage((t + 3) & (STAGES - 1), t + 3);

        uint32_t stA = sbase + (uint32_t)(t & (STAGES - 1)) * STAGE_BYTES;
        uint32_t stB = stA + 8192u;

        #pragma unroll
        for (int ks = 0; ks < 4; ks++) {
            uint32_t a[4], b[2][4];
            int cha = (2 * ks + csel_a) ^ rxa;
            ldm_x4(a, stA + rowa_off + (uint32_t)(cha << 4));
            int chb = (2 * ks + csel_b) ^ rxb;
            ldm_x4(b[0], stB + rowb_off[0] + (uint32_t)(chb << 4));
            ldm_x4(b[1], stB + rowb_off[1] + (uint32_t)(chb << 4));
            if (t < 8) {
                mma16816(accE[0], a, &b[0][0]);
                mma16816(accE[1], a, &b[0][2]);
                mma16816(accE[2], a, &b[1][0]);
                mma16816(accE[3], a, &b[1][2]);
            } else {
                mma16816(accO[0], a, &b[0][0]);
                mma16816(accO[1], a, &b[0][2]);
                mma16816(accO[2], a, &b[1][0]);
                mma16816(accO[3], a, &b[1][2]);
            }
        }
    }

    // ---- epilogue: butterfly + LN + 4-region store
    const int r0 = m0 + wm * 16 + (lane >> 2);
    const float rs0 = g_rs[r0];
    const float rs1 = g_rs[r0 + 8];
    const int kw = k0 + wn * 32 + 2 * (lane & 3);
    #pragma unroll
    for (int nf = 0; nf < 4; nf++) {
        int k = kw + nf * 8;                       // even, 0..510
        float g0 = __ldg(gamma + k),     be0 = __ldg(beta + k);
        float g1 = __ldg(gamma + k + 1), be1 = __ldg(beta + k + 1);
        float gm1 = __ldg(gamma + 2047 - k), bm1 = __ldg(beta + 2047 - k);
        float gm0 = 0.0f, bm0 = 0.0f;
        if (k > 0) { gm0 = __ldg(gamma + 2048 - k); bm0 = __ldg(beta + 2048 - k); }
        float gb0 = __ldg(gamma + 1024 - k), bb0 = __ldg(beta + 1024 - k);
        float gb1 = __ldg(gamma + 1023 - k), bb1 = __ldg(beta + 1023 - k);
        float gf0 = __ldg(gamma + 1024 + k), bf0 = __ldg(beta + 1024 + k);
        float gf1 = __ldg(gamma + 1025 + k), bf1 = __ldg(beta + 1025 + k);
        #pragma unroll
        for (int rp = 0; rp < 2; rp++) {
            float* o = out + (size_t)(r0 + rp * 8) * CDIM;
            float E0 = accE[nf][rp * 2],     O0 = accO[nf][rp * 2];
            float E1 = accE[nf][rp * 2 + 1], O1 = accO[nf][rp * 2 + 1];
            float r = rp ? rs1 : rs0;
            float z0 = (E0 + O0) * r, z1 = (E1 + O1) * r;
            float w0 = (E0 - O0) * r, w1 = (E1 - O1) * r;
            *(float2*)(o + k) = make_float2(z0 * g0 + be0, z1 * g1 + be1);
            o[2047 - k] = z1 * gm1 + bm1;
            if (k > 0) o[2048 - k] = z0 * gm0 + bm0;
            o[1024 - k] = w0 * gb0 + bb0;
            o[1023 - k] = w1 * gb1 + bb1;
            if (k > 0) *(float2*)(o + 1024 + k) = make_float2(w0 * gf0 + bf0, w1 * gf1 + bf1);
            else       o[1025] = w1 * gf1 + bf1;
        }
    }
}

// ---------------------------------------------------------------- launch
extern "C" void kernel_launch(void* const* d_in, const int* in_sizes, int n_in,
                              void* d_out, int out_size) {
    const float* x     = (const float*)d_in[0];
    const float* gamma = (const float*)d_in[1];
    const float* beta  = (const float*)d_in[2];
    float* out = (float*)d_out;

    prep_kernel<<<ROWS + TBLOCKS, 256>>>(x, gamma, beta, out);

    cudaFuncSetAttribute(gemm_ln_kernel, cudaFuncAttributeMaxDynamicSharedMemorySize, SMEM_SZ);
    dim3 grid(512 / BNK, ROWS / BM);   // (8, 256): k fastest -> A rows shared in L2
    gemm_ln_kernel<<<grid, 256, SMEM_SZ>>>(gamma, beta, out);
}

// round 9
// speedup vs baseline: 1.2816x; 1.0883x over previous
#include <cuda_runtime.h>
#include <cuda_fp16.h>
#include <math.h>
#include <stdint.h>

// out = LayerNorm(Re(FFT(x, axis=-1))), x: (4,4096,2048) fp32.
// Radix-2 split of the folded cosine transform:
//   s[c] = x[c]+x[2048-c] (c=1..1023), s[1024]=x[1024]; c=0 dropped (== mean)
//   Se[0]=s[1024], Se[j]=s[2j] (j=1..511);  Be[k][0]=(-1)^k, Be[k][j]=cospi(kj/512)
//   So[d]=s[2d+1] (d=0..511);               Bo[k][d]=cospi(k(2d+1)/1024)
//   E[k]=Se.Be[k], O[k]=So.Bo[k];  y-mu: [k]=E+O, [1024-k]=E-O (k=0..511)
//   y[512]-mu = sum_j Se[j](-1)^j (prep, closed form); mirror y[2048-k]=y[k]
//   var = 0.5*(sum x^2 + sum x[c]x[(2048-c)%2048]) - x[0]^2
// GEMM: M=16384, K=512 x2 phases, N=512, fp16/fp32 mma.sync.
// CTA tile 64m x 64n, 8 warps (16m x 32n), 4-stage cp.async, 3 CTAs/SM.

#define ROWS 16384
#define CDIM 2048
#define BM   64
#define BNK  64
#define BKC  64
#define NT   16          // chunks: 8 E + 8 O
#define STAGES 4
#define TBLOCKS 2048     // table-init blocks (1 half per thread)
#define EPS  1e-5f

__device__ __half g_S[(size_t)ROWS * 1024];  // [m][0..511]=Se, [512..1023]=So
__device__ __half g_T[(size_t)512 * 1024];   // [k][0..511]=Be, [512..1023]=Bo
__device__ float  g_rs[ROWS];

__device__ __forceinline__ uint32_t smem_u32(const void* p) {
    uint32_t a;
    asm("{ .reg .u64 t; cvta.to.shared.u64 t, %1; cvt.u32.u64 %0, t; }" : "=r"(a) : "l"(p));
    return a;
}
__device__ __forceinline__ void cp16(uint32_t s, const void* g) {
    asm volatile("cp.async.cg.shared.global [%0], [%1], 16;" :: "r"(s), "l"(g) : "memory");
}
#define CP_COMMIT() asm volatile("cp.async.commit_group;" ::: "memory")

__device__ __forceinline__ void ldm_x4(uint32_t* r, uint32_t a) {
    asm volatile("ldmatrix.sync.aligned.m8n8.x4.shared.b16 {%0,%1,%2,%3}, [%4];"
                 : "=r"(r[0]), "=r"(r[1]), "=r"(r[2]), "=r"(r[3]) : "r"(a));
}
__device__ __forceinline__ void mma16816(float* c, const uint32_t* a, const uint32_t* b) {
    asm volatile("mma.sync.aligned.m16n8k16.row.col.f32.f16.f16.f32 "
                 "{%0,%1,%2,%3}, {%4,%5,%6,%7}, {%8,%9}, {%0,%1,%2,%3};"
                 : "+f"(c[0]), "+f"(c[1]), "+f"(c[2]), "+f"(c[3])
                 : "r"(a[0]), "r"(a[1]), "r"(a[2]), "r"(a[3]), "r"(b[0]), "r"(b[1]));
}

// ---------------------------------------------------------------- prep + table
// blocks [0,ROWS): register-only fold/stats, 1 row per 256-thread block.
// blocks [ROWS,ROWS+TBLOCKS): tables. Args of cospif exact in fp32 (<2^24).
__global__ __launch_bounds__(256) void prep_kernel(const float* __restrict__ x,
                                                   const float* __restrict__ gamma,
                                                   const float* __restrict__ beta,
                                                   float* __restrict__ out) {
    if (blockIdx.x >= ROWS) {
        int idx = (blockIdx.x - ROWS) * 256 + threadIdx.x;   // < 512*1024
        int k = idx >> 10;
        int j = idx & 1023;
        float v;
        if (j < 512) {
            int jj = j ? j : 512;                 // j=0 column: cospi(k) = (-1)^k
            v = cospif((float)(k * jj) * (1.0f / 512.0f));
        } else {
            v = cospif((float)(k * (2 * (j - 512) + 1)) * (1.0f / 1024.0f));
        }
        g_T[idx] = __float2half(v);
        return;
    }

    __shared__ float w1[8], w2[8], w3[8];
    const int row = blockIdx.x;
    const int tid = threadIdx.x;
    const float* xr = x + (size_t)row * CDIM;
    const float4* x4 = (const float4*)xr;

    float4 f4 = x4[tid];          // x[4t .. 4t+3]      (covers 0..1023)
    float4 b4 = x4[511 - tid];    // x[2044-4t..2047-4t] (covers 1024..2047)
    float xm = 0.0f, x1024 = 0.0f;
    if (tid > 0) xm = xr[2048 - 4 * tid];
    else         x1024 = xr[1024];

    float sumsq = f4.x * f4.x + f4.y * f4.y + f4.z * f4.z + f4.w * f4.w
                + b4.x * b4.x + b4.y * b4.y + b4.z * b4.z + b4.w * b4.w;

    // folds: s[c] = x[c] + x[2048-c]
    float s0 = f4.x + xm;      // s[4t]   (t>0)
    float s1 = f4.y + b4.w;    // s[4t+1]
    float s2 = f4.z + b4.z;    // s[4t+2]
    float s3 = f4.w + b4.y;    // s[4t+3]

    float r, e;
    __half2 he, ho;
    if (tid > 0) {
        r = f4.x * xm + f4.y * b4.w + f4.z * b4.z + f4.w * b4.y;
        e = s0 - s2;                               // (-1)^(2t) s[4t] + (-1)^(2t+1) s[4t+2]
        he = __floats2half2_rn(s0, s2);            // Se[2t], Se[2t+1]
    } else {
        r = f4.y * b4.w + f4.z * b4.z + f4.w * b4.y
          + 0.5f * (f4.x * f4.x + x1024 * x1024);  // x0^2, x1024^2 (doubled below)
        e = x1024 - s2;                            // j=0: +Se[0]; j=1: -Se[1]
        he = __floats2half2_rn(x1024, s2);         // Se[0]=s[1024], Se[1]=s[2]
    }
    ho = __floats2half2_rn(s1, s3);                // So[2t], So[2t+1]

    __half* Sr = g_S + (size_t)row * 1024;
    *(__half2*)(Sr + 2 * tid) = he;
    *(__half2*)(Sr + 512 + 2 * tid) = ho;

    #pragma unroll
    for (int o = 16; o > 0; o >>= 1) {
        sumsq += __shfl_xor_sync(0xffffffffu, sumsq, o);
        r     += __shfl_xor_sync(0xffffffffu, r, o);
        e     += __shfl_xor_sync(0xffffffffu, e, o);
    }
    if ((tid & 31) == 0) { w1[tid >> 5] = sumsq; w2[tid >> 5] = r; w3[tid >> 5] = e; }
    __syncthreads();
    if (tid == 0) {
        float a = 0.0f, rr = 0.0f, e5 = 0.0f;
        #pragma unroll
        for (int i = 0; i < 8; i++) { a += w1[i]; rr += w2[i]; e5 += w3[i]; }
        float mu = f4.x;                       // x[0]
        float var = 0.5f * (a + 2.0f * rr) - mu * mu;
        float rs = rsqrtf(var + EPS);
        g_rs[row] = rs;
        float z = e5 * rs;                     // y[512]-mu
        float* orow = out + (size_t)row * CDIM;
        orow[512]  = z * gamma[512]  + beta[512];
        orow[1536] = z * gamma[1536] + beta[1536];
    }
}

// ---------------------------------------------------------------- GEMM + LN
// stage: A 64x64 fp16 (8KB) + B 64x64 fp16 (8KB) = 16KB; rows 128B, xor swizzle
#define STAGE_BYTES 16384
#define SMEM_SZ (STAGES * STAGE_BYTES)

__global__ __launch_bounds__(256, 3) void gemm_ln_kernel(const float* __restrict__ gamma,
                                                         const float* __restrict__ beta,
                                                         float* __restrict__ out) {
    extern __shared__ __align__(1024) uint8_t smem[];
    const uint32_t sbase = smem_u32(smem);
    const int tid = threadIdx.x;
    const int wid = tid >> 5;
    const int lane = tid & 31;
    const int m0 = blockIdx.y * BM;
    const int k0 = blockIdx.x * BNK;     // k-column tile base (0..511)

    // ---- producers: 64 rows x 8 chunks(16B) each for A and B; 2 chunks/thread
    const int prow = tid >> 2;
    const int pc0 = (tid & 3) * 2;
    const __half* gA = g_S + (size_t)(m0 + prow) * 1024 + pc0 * 8;
    const __half* gB = g_T + (size_t)(k0 + prow) * 1024 + pc0 * 8;
    const uint32_t pso = (uint32_t)prow * 128u;
    const int prx = prow & 7;

    // ---- consumers: 8 warps = 4 (m) x 2 (n); warp tile 16m x 32n
    const int wm = wid & 3;
    const int wn = wid >> 2;
    const uint32_t rowa_off = (uint32_t)(wm * 16 + (lane & 15)) * 128u;
    const int rxa = lane & 7;
    const int csel_a = lane >> 4;
    uint32_t rowb_off[2];
    {
        int nb = wn * 32 + ((lane >> 4) << 3) + (lane & 7);
        rowb_off[0] = (uint32_t)nb * 128u;
        rowb_off[1] = (uint32_t)(nb + 16) * 128u;
    }
    const int rxb = lane & 7;
    const int csel_b = (lane >> 3) & 1;

    float accE[4][4], accO[4][4];
    #pragma unroll
    for (int j = 0; j < 4; j++)
        #pragma unroll
        for (int r = 0; r < 4; r++) { accE[j][r] = 0.0f; accO[j][r] = 0.0f; }

    auto load_stage = [&](int stage, int t) {
        uint32_t sA = sbase + (uint32_t)stage * STAGE_BYTES;
        uint32_t sB = sA + 8192u;
        int koff = (t >> 3) * 512 + (t & 7) * BKC;    // phase*512 + kc*64
        const __half* pa = gA + koff;
        const __half* pb = gB + koff;
        #pragma unroll
        for (int i = 0; i < 2; i++) {
            uint32_t so = pso + (uint32_t)(((pc0 + i) ^ prx) << 4);
            cp16(sA + so, pa + i * 8);
            cp16(sB + so, pb + i * 8);
        }
        CP_COMMIT();
    };

    load_stage(0, 0);
    load_stage(1, 1);
    load_stage(2, 2);

    for (int t = 0; t < NT; t++) {
        if (t < NT - 2)       asm volatile("cp.async.wait_group 2;" ::: "memory");
        else if (t == NT - 2) asm volatile("cp.async.wait_group 1;" ::: "memory");
        else                  asm volatile("cp.async.wait_group 0;" ::: "memory");
        __syncthreads();
        if (t + 3 < NT) load_stage((t + 3) & (STAGES - 1), t + 3);

        uint32_t stA = sbase + (uint32_t)(t & (STAGES - 1)) * STAGE_BYTES;
        uint32_t stB = stA + 8192u;

        #pragma unroll
        for (int ks = 0; ks < 4; ks++) {
            uint32_t a[4], b[2][4];
            int cha = (2 * ks + csel_a) ^ rxa;
            ldm_x4(a, stA + rowa_off + (uint32_t)(cha << 4));
            int chb = (2 * ks + csel_b) ^ rxb;
            ldm_x4(b[0], stB + rowb_off[0] + (uint32_t)(chb << 4));
            ldm_x4(b[1], stB + rowb_off[1] + (uint32_t)(chb << 4));
            if (t < 8) {
                mma16816(accE[0], a, &b[0][0]);
                mma16816(accE[1], a, &b[0][2]);
                mma16816(accE[2], a, &b[1][0]);
                mma16816(accE[3], a, &b[1][2]);
            } else {
                mma16816(accO[0], a, &b[0][0]);
                mma16816(accO[1], a, &b[0][2]);
                mma16816(accO[2], a, &b[1][0]);
                mma16816(accO[3], a, &b[1][2]);
            }
        }
    }

    // ---- epilogue: butterfly + LN + 4-region store
    const int r0 = m0 + wm * 16 + (lane >> 2);
    const float rs0 = g_rs[r0];
    const float rs1 = g_rs[r0 + 8];
    const int kw = k0 + wn * 32 + 2 * (lane & 3);
    #pragma unroll
    for (int nf = 0; nf < 4; nf++) {
        int k = kw + nf * 8;                       // even, 0..510
        float g0 = __ldg(gamma + k),     be0 = __ldg(beta + k);
        float g1 = __ldg(gamma + k + 1), be1 = __ldg(beta + k + 1);
        float gm1 = __ldg(gamma + 2047 - k), bm1 = __ldg(beta + 2047 - k);
        float gm0 = 0.0f, bm0 = 0.0f;
        if (k > 0) { gm0 = __ldg(gamma + 2048 - k); bm0 = __ldg(beta + 2048 - k); }
        float gb0 = __ldg(gamma + 1024 - k), bb0 = __ldg(beta + 1024 - k);
        float gb1 = __ldg(gamma + 1023 - k), bb1 = __ldg(beta + 1023 - k);
        float gf0 = __ldg(gamma + 1024 + k), bf0 = __ldg(beta + 1024 + k);
        float gf1 = __ldg(gamma + 1025 + k), bf1 = __ldg(beta + 1025 + k);
        #pragma unroll
        for (int rp = 0; rp < 2; rp++) {
            float* o = out + (size_t)(r0 + rp * 8) * CDIM;
            float E0 = accE[nf][rp * 2],     O0 = accO[nf][rp * 2];
            float E1 = accE[nf][rp * 2 + 1], O1 = accO[nf][rp * 2 + 1];
            float r = rp ? rs1 : rs0;
            float z0 = (E0 + O0) * r, z1 = (E1 + O1) * r;
            float w0 = (E0 - O0) * r, w1 = (E1 - O1) * r;
            *(float2*)(o + k) = make_float2(z0 * g0 + be0, z1 * g1 + be1);
            o[2047 - k] = z1 * gm1 + bm1;
            if (k > 0) o[2048 - k] = z0 * gm0 + bm0;
            o[1024 - k] = w0 * gb0 + bb0;
            o[1023 - k] = w1 * gb1 + bb1;
            if (k > 0) *(float2*)(o + 1024 + k) = make_float2(w0 * gf0 + bf0, w1 * gf1 + bf1);
            else       o[1025] = w1 * gf1 + bf1;
        }
    }
}

// ---------------------------------------------------------------- launch
extern "C" void kernel_launch(void* const* d_in, const int* in_sizes, int n_in,
                              void* d_out, int out_size) {
    const float* x     = (const float*)d_in[0];
    const float* gamma = (const float*)d_in[1];
    const float* beta  = (const float*)d_in[2];
    float* out = (float*)d_out;

    prep_kernel<<<ROWS + TBLOCKS, 256>>>(x, gamma, beta, out);

    cudaFuncSetAttribute(gemm_ln_kernel, cudaFuncAttributeMaxDynamicSharedMemorySize, SMEM_SZ);
    dim3 grid(512 / BNK, ROWS / BM);   // (8, 256): k fastest -> A rows shared in L2
    gemm_ln_kernel<<<grid, 256, SMEM_SZ>>>(gamma, beta, out);
}